// round 1
// baseline (speedup 1.0000x reference)
#include <cuda_runtime.h>

// Problem constants
#define DIM   (1 << 22)        // 2^22 = 4194304
#define BATCH 16
#define HALF4 ((DIM / 2) * BATCH / 4)   // 8388608 float4s per half-state

// Scratch for precomputed cos(theta/2), sin(theta/2)
__device__ float g_cos[BATCH];
__device__ float g_sin[BATCH];

__global__ void precompute_trig(const float* __restrict__ theta) {
    int i = threadIdx.x;
    if (i < BATCH) {
        float t = theta[i] * 0.5f;
        g_cos[i] = cosf(t);
        g_sin[i] = sinf(t);
    }
}

// Each thread handles one float4 (4 batch entries) of one row j in the lower
// half, paired with row j + DIM/2 in the upper half.
// Memory layout (float4 index space, H = HALF4):
//   inputs : re[t], re[t+H], im[t], im[t+H]
//   outputs: out_re lower = out[t], out_re upper = out[t+H]
//            out_im lower = out[2H+t], out_im upper = out[3H+t]
__global__ __launch_bounds__(256) void rot_kernel(
    const float4* __restrict__ re,
    const float4* __restrict__ im,
    float4* __restrict__ out)
{
    int t = blockIdx.x * 256 + threadIdx.x;
    int b4 = t & 3;  // which float4 within the 16-wide batch row

    float4 c = reinterpret_cast<const float4*>(g_cos)[b4];
    float4 s = reinterpret_cast<const float4*>(g_sin)[b4];

    // 4 independent 128-bit loads (MLP=4)
    float4 re0 = re[t];
    float4 re1 = re[t + HALF4];
    float4 im0 = im[t];
    float4 im1 = im[t + HALF4];

    float4 or0, or1, oi0, oi1;
#define ROT_COMP(f)                                   \
    or0.f = fmaf(c.f, re0.f,  s.f * im1.f);           \
    oi0.f = fmaf(c.f, im0.f, -s.f * re1.f);           \
    or1.f = fmaf(c.f, re1.f,  s.f * im0.f);           \
    oi1.f = fmaf(c.f, im1.f, -s.f * re0.f);
    ROT_COMP(x) ROT_COMP(y) ROT_COMP(z) ROT_COMP(w)
#undef ROT_COMP

    out[t]             = or0;
    out[t + HALF4]     = or1;
    out[2 * HALF4 + t] = oi0;
    out[3 * HALF4 + t] = oi1;
}

extern "C" void kernel_launch(void* const* d_in, const int* in_sizes, int n_in,
                              void* d_out, int out_size) {
    const float* theta = (const float*)d_in[0];
    const float4* re   = (const float4*)d_in[1];
    const float4* im   = (const float4*)d_in[2];
    float4* out        = (float4*)d_out;

    precompute_trig<<<1, 32>>>(theta);
    rot_kernel<<<HALF4 / 256, 256>>>(re, im, out);
}

// round 2
// speedup vs baseline: 1.0026x; 1.0026x over previous
#include <cuda_runtime.h>

// Problem constants
#define DIM   (1 << 22)        // 2^22 = 4194304
#define BATCH 16
#define HALF4 ((DIM / 2) * BATCH / 4)   // 8388608 float4s per half-state

// Fused kernel: per-block trig precompute (16 cos/sin via MUFU, broadcast
// through smem) + streaming rotation. Each thread handles one float4
// (4 batch entries) of one row j in the lower half, paired with row
// j + DIM/2 in the upper half.
//
// Memory layout (float4 index space, H = HALF4):
//   inputs : re[t], re[t+H], im[t], im[t+H]
//   outputs: out_re lower = out[t], out_re upper = out[t+H]
//            out_im lower = out[2H+t], out_im upper = out[3H+t]
__global__ __launch_bounds__(256) void rot_kernel(
    const float* __restrict__ theta,
    const float4* __restrict__ re,
    const float4* __restrict__ im,
    float4* __restrict__ out)
{
    __shared__ float sc[BATCH];
    __shared__ float ss[BATCH];

    if (threadIdx.x < BATCH) {
        float t = theta[threadIdx.x] * 0.5f;   // L2-resident after first wave
        sc[threadIdx.x] = cosf(t);
        ss[threadIdx.x] = sinf(t);
    }
    __syncthreads();

    int t  = blockIdx.x * 256 + threadIdx.x;
    int b4 = t & 3;  // which float4 within the 16-wide batch row

    float4 c = reinterpret_cast<const float4*>(sc)[b4];
    float4 s = reinterpret_cast<const float4*>(ss)[b4];

    // 4 independent 128-bit streaming loads (MLP=4, evict-first)
    float4 re0 = __ldcs(&re[t]);
    float4 re1 = __ldcs(&re[t + HALF4]);
    float4 im0 = __ldcs(&im[t]);
    float4 im1 = __ldcs(&im[t + HALF4]);

    float4 or0, or1, oi0, oi1;
#define ROT_COMP(f)                                   \
    or0.f = fmaf(c.f, re0.f,  s.f * im1.f);           \
    oi0.f = fmaf(c.f, im0.f, -s.f * re1.f);           \
    or1.f = fmaf(c.f, re1.f,  s.f * im0.f);           \
    oi1.f = fmaf(c.f, im1.f, -s.f * re0.f);
    ROT_COMP(x) ROT_COMP(y) ROT_COMP(z) ROT_COMP(w)
#undef ROT_COMP

    // Streaming stores (evict-first: no point caching write-allocated lines)
    __stcs(&out[t],             or0);
    __stcs(&out[t + HALF4],     or1);
    __stcs(&out[2 * HALF4 + t], oi0);
    __stcs(&out[3 * HALF4 + t], oi1);
}

extern "C" void kernel_launch(void* const* d_in, const int* in_sizes, int n_in,
                              void* d_out, int out_size) {
    const float* theta = (const float*)d_in[0];
    const float4* re   = (const float4*)d_in[1];
    const float4* im   = (const float4*)d_in[2];
    float4* out        = (float4*)d_out;

    rot_kernel<<<HALF4 / 256, 256>>>(theta, re, im, out);
}

// round 3
// speedup vs baseline: 1.0028x; 1.0002x over previous
#include <cuda_runtime.h>

// Problem constants
#define DIM   (1 << 22)        // 2^22 = 4194304
#define BATCH 16
#define HALF4 ((DIM / 2) * BATCH / 4)   // 8388608 float4s per half-state

// Fused kernel: per-block trig precompute (16 cos/sin, broadcast via smem)
// + streaming rotation with default cache policy (measured fastest: 85.8%
// DRAM vs 84.5% with .cs hints).
//
// Each thread handles one float4 (4 batch entries) of one row j in the lower
// half, paired with row j + DIM/2 in the upper half.
//
// Memory layout (float4 index space, H = HALF4):
//   inputs : re[t], re[t+H], im[t], im[t+H]
//   outputs: out_re lower = out[t], out_re upper = out[t+H]
//            out_im lower = out[2H+t], out_im upper = out[3H+t]
__global__ __launch_bounds__(256) void rot_kernel(
    const float* __restrict__ theta,
    const float4* __restrict__ re,
    const float4* __restrict__ im,
    float4* __restrict__ out)
{
    __shared__ float sc[BATCH];
    __shared__ float ss[BATCH];

    if (threadIdx.x < BATCH) {
        float t = theta[threadIdx.x] * 0.5f;   // L2-resident after first wave
        sc[threadIdx.x] = cosf(t);
        ss[threadIdx.x] = sinf(t);
    }
    __syncthreads();

    int t  = blockIdx.x * 256 + threadIdx.x;
    int b4 = t & 3;  // which float4 within the 16-wide batch row

    float4 c = reinterpret_cast<const float4*>(sc)[b4];
    float4 s = reinterpret_cast<const float4*>(ss)[b4];

    // 4 independent 128-bit loads (MLP=4), default caching
    float4 re0 = re[t];
    float4 re1 = re[t + HALF4];
    float4 im0 = im[t];
    float4 im1 = im[t + HALF4];

    float4 or0, or1, oi0, oi1;
#define ROT_COMP(f)                                   \
    or0.f = fmaf(c.f, re0.f,  s.f * im1.f);           \
    oi0.f = fmaf(c.f, im0.f, -s.f * re1.f);           \
    or1.f = fmaf(c.f, re1.f,  s.f * im0.f);           \
    oi1.f = fmaf(c.f, im1.f, -s.f * re0.f);
    ROT_COMP(x) ROT_COMP(y) ROT_COMP(z) ROT_COMP(w)
#undef ROT_COMP

    out[t]             = or0;
    out[t + HALF4]     = or1;
    out[2 * HALF4 + t] = oi0;
    out[3 * HALF4 + t] = oi1;
}

extern "C" void kernel_launch(void* const* d_in, const int* in_sizes, int n_in,
                              void* d_out, int out_size) {
    const float* theta = (const float*)d_in[0];
    const float4* re   = (const float4*)d_in[1];
    const float4* im   = (const float4*)d_in[2];
    float4* out        = (float4*)d_out;

    rot_kernel<<<HALF4 / 256, 256>>>(theta, re, im, out);
}

// round 4
// speedup vs baseline: 1.0030x; 1.0002x over previous
#include <cuda_runtime.h>

// Problem constants
#define DIM   (1 << 22)        // 2^22 = 4194304
#define BATCH 16
#define HALF4 ((DIM / 2) * BATCH / 4)   // 8388608 float4s per half-state
#define TPB   128                        // higher occupancy granularity (81% theo)

// Fused kernel: streaming rotation with per-block trig broadcast via smem.
// Global loads are issued BEFORE the barrier (they don't depend on trig),
// so memory latency overlaps the cos/sin compute + barrier.
//
// Each thread handles one float4 (4 batch entries) of one row j in the lower
// half, paired with row j + DIM/2 in the upper half.
//
// Memory layout (float4 index space, H = HALF4):
//   inputs : re[t], re[t+H], im[t], im[t+H]
//   outputs: out_re lower = out[t], out_re upper = out[t+H]
//            out_im lower = out[2H+t], out_im upper = out[3H+t]
__global__ __launch_bounds__(TPB) void rot_kernel(
    const float* __restrict__ theta,
    const float4* __restrict__ re,
    const float4* __restrict__ im,
    float4* __restrict__ out)
{
    __shared__ float sc[BATCH];
    __shared__ float ss[BATCH];

    int t  = blockIdx.x * TPB + threadIdx.x;

    // 4 independent 128-bit loads issued first (MLP=4, latency overlapped
    // with trig + barrier below)
    float4 re0 = re[t];
    float4 re1 = re[t + HALF4];
    float4 im0 = im[t];
    float4 im1 = im[t + HALF4];

    if (threadIdx.x < BATCH) {
        float th = theta[threadIdx.x] * 0.5f;  // L2-resident after first wave
        sc[threadIdx.x] = cosf(th);
        ss[threadIdx.x] = sinf(th);
    }
    __syncthreads();

    int b4 = t & 3;  // which float4 within the 16-wide batch row
    float4 c = reinterpret_cast<const float4*>(sc)[b4];
    float4 s = reinterpret_cast<const float4*>(ss)[b4];

    float4 or0, or1, oi0, oi1;
#define ROT_COMP(f)                                   \
    or0.f = fmaf(c.f, re0.f,  s.f * im1.f);           \
    oi0.f = fmaf(c.f, im0.f, -s.f * re1.f);           \
    or1.f = fmaf(c.f, re1.f,  s.f * im0.f);           \
    oi1.f = fmaf(c.f, im1.f, -s.f * re0.f);
    ROT_COMP(x) ROT_COMP(y) ROT_COMP(z) ROT_COMP(w)
#undef ROT_COMP

    out[t]             = or0;
    out[t + HALF4]     = or1;
    out[2 * HALF4 + t] = oi0;
    out[3 * HALF4 + t] = oi1;
}

extern "C" void kernel_launch(void* const* d_in, const int* in_sizes, int n_in,
                              void* d_out, int out_size) {
    const float* theta = (const float*)d_in[0];
    const float4* re   = (const float4*)d_in[1];
    const float4* im   = (const float4*)d_in[2];
    float4* out        = (float4*)d_out;

    rot_kernel<<<HALF4 / TPB, TPB>>>(theta, re, im, out);
}